// round 2
// baseline (speedup 1.0000x reference)
#include <cuda_runtime.h>
#include <cuda_bf16.h>
#include <math.h>

// ------------ problem constants ------------
#define NFRM   256                  // B*T
#define ECOLS  147456               // NFRM * 576 edge columns
#define NCOLS  6144                 // NFRM * 24 node columns

// ------------ device scratch ------------
__device__ float g_edge_t[128 * ECOLS];   // transposed edge_resnet [d][col]
__device__ float g_epre  [128 * ECOLS];   // msg_We @ edge + msg_b (loop-invariant)
__device__ float g_hedge [128 * ECOLS];   // hidden edge states
__device__ float g_gate  [ECOLS];
__device__ float g_node0 [128 * NCOLS];   // transposed node_resnet
__device__ float g_hnode [128 * NCOLS];
__device__ float g_nh    [128 * NCOLS];   // msg_Wh @ h_node
__device__ float g_mv    [128 * NCOLS];
__device__ float g_gi    [384 * NCOLS];
__device__ float g_gh    [384 * NCOLS];
__device__ float g_xg    [512 * NCOLS];   // lstm_Wih @ h_node + bih + bhh
__device__ float g_h     [128 * 192];
__device__ float g_c     [128 * 192];
__device__ float g_hist  [128 * 6144];    // h history [j][t*192 + b*24 + n]

__device__ __forceinline__ float sigm(float x) { return 1.f / (1.f + expf(-x)); }

__device__ __forceinline__ void ffma2(unsigned long long& acc,
                                      unsigned long long a, unsigned long long b) {
    asm("fma.rn.f32x2 %0, %1, %2, %0;" : "+l"(acc) : "l"(a), "l"(b));
}
__device__ __forceinline__ unsigned long long pack2(float x, float y) {
    unsigned long long r;
    asm("mov.b64 %0, {%1, %2};" : "=l"(r) : "f"(x), "f"(y));
    return r;
}
__device__ __forceinline__ float2 unpack2(unsigned long long v) {
    float2 f;
    asm("mov.b64 {%0, %1}, %2;" : "=f"(f.x), "=f"(f.y) : "l"(v));
    return f;
}

// ------------ transposes ------------
__global__ void __launch_bounds__(256) tr_edge_k(const float* __restrict__ in)
{
    int o = blockIdx.x * 256 + threadIdx.x;          // < 128*ECOLS
    int d = o / ECOLS; int c = o - d * ECOLS;
    int f = c / 576;   int vw = c - f * 576;
    g_edge_t[o] = in[f * 73728 + d * 576 + vw];
}

__global__ void __launch_bounds__(256) tr_node_k(const float* __restrict__ in)
{
    int o = blockIdx.x * 256 + threadIdx.x;          // < 128*NCOLS
    int d = o / NCOLS; int c = o - d * NCOLS;
    int f = c / 24;    int n = c - f * 24;
    float v = in[f * 3072 + d * 24 + n];
    g_node0[o] = v;
    g_hnode[o] = v;
}

// ------------ SGEMM: Y[M,cols] = W[M,128] @ X[128,cols] (+bias,+bias2) ------------
// grid (cols/64, M/64), block 256.  f32x2 packed accumulation.
__global__ void __launch_bounds__(256) sgemm_k(const float* __restrict__ W,
                                               const float* __restrict__ X,
                                               const float* __restrict__ bias,
                                               const float* __restrict__ bias2,
                                               float* __restrict__ Y, int cols)
{
    __shared__ __align__(16) float sW[64][33];
    __shared__ __align__(16) float sX[32][64];
    int tid = threadIdx.x;
    int c0 = blockIdx.x * 64;
    int m0 = blockIdx.y * 64;
    int tx = tid & 15, ty = tid >> 4;
    unsigned long long acc[4][2];
#pragma unroll
    for (int r = 0; r < 4; r++) { acc[r][0] = 0ull; acc[r][1] = 0ull; }

    for (int kt = 0; kt < 4; kt++) {
#pragma unroll
        for (int i = 0; i < 2; i++) {
            int idx = tid + i * 256;                 // 512 float4 of W tile
            int r = idx >> 3, kq = (idx & 7) << 2;
            float4 v = *(const float4*)(W + (m0 + r) * 128 + kt * 32 + kq);
            sW[r][kq] = v.x; sW[r][kq + 1] = v.y; sW[r][kq + 2] = v.z; sW[r][kq + 3] = v.w;
        }
#pragma unroll
        for (int i = 0; i < 2; i++) {
            int idx = tid + i * 256;                 // 512 float4 of X tile
            int k = idx >> 4, j = (idx & 15) << 2;
            *(float4*)&sX[k][j] = *(const float4*)(X + (kt * 32 + k) * cols + c0 + j);
        }
        __syncthreads();
#pragma unroll
        for (int k = 0; k < 32; k++) {
            unsigned long long b0 = *(const unsigned long long*)&sX[k][tx << 2];
            unsigned long long b1 = *(const unsigned long long*)&sX[k][(tx << 2) + 2];
#pragma unroll
            for (int r = 0; r < 4; r++) {
                float a = sW[(ty << 2) + r][k];
                unsigned long long a2 = pack2(a, a);
                ffma2(acc[r][0], a2, b0);
                ffma2(acc[r][1], a2, b1);
            }
        }
        __syncthreads();
    }
#pragma unroll
    for (int r = 0; r < 4; r++) {
        int row = m0 + (ty << 2) + r;
        float bs = (bias ? bias[row] : 0.f) + (bias2 ? bias2[row] : 0.f);
        float2 p0 = unpack2(acc[r][0]);
        float2 p1 = unpack2(acc[r][1]);
        float4 v = make_float4(p0.x + bs, p0.y + bs, p1.x + bs, p1.y + bs);
        *(float4*)(Y + row * cols + c0 + (tx << 2)) = v;
    }
}

// ------------ fused link: gate = pair_mask * sigmoid(W2 . relu(W1@E + b1) + b2) ------------
// grid ECOLS/64, block 256. 64 edge columns per block (each block within one frame).
__global__ void __launch_bounds__(256) link_k(const float* __restrict__ E,
                                              const float* __restrict__ W1,
                                              const float* __restrict__ b1,
                                              const float* __restrict__ W2,
                                              const float* __restrict__ b2p,
                                              const int* __restrict__ nnum)
{
    __shared__ __align__(16) float sW[128][33];
    __shared__ __align__(16) float sX[32][64];
    __shared__ float sRed[16][64];
    int tid = threadIdx.x;
    int c0 = blockIdx.x * 64;
    int tx = tid & 15, ty = tid >> 4;
    unsigned long long acc[8][2];
#pragma unroll
    for (int r = 0; r < 8; r++) { acc[r][0] = 0ull; acc[r][1] = 0ull; }

    for (int kt = 0; kt < 4; kt++) {
#pragma unroll
        for (int i = 0; i < 4; i++) {
            int idx = tid + i * 256;                 // 1024 float4 of W1 (128 x 32)
            int r = idx >> 3, kq = (idx & 7) << 2;
            float4 v = *(const float4*)(W1 + r * 128 + kt * 32 + kq);
            sW[r][kq] = v.x; sW[r][kq + 1] = v.y; sW[r][kq + 2] = v.z; sW[r][kq + 3] = v.w;
        }
#pragma unroll
        for (int i = 0; i < 2; i++) {
            int idx = tid + i * 256;
            int k = idx >> 4, j = (idx & 15) << 2;
            *(float4*)&sX[k][j] = *(const float4*)(E + (kt * 32 + k) * ECOLS + c0 + j);
        }
        __syncthreads();
#pragma unroll
        for (int k = 0; k < 32; k++) {
            unsigned long long b0 = *(const unsigned long long*)&sX[k][tx << 2];
            unsigned long long b1v = *(const unsigned long long*)&sX[k][(tx << 2) + 2];
#pragma unroll
            for (int r = 0; r < 8; r++) {
                float a = sW[ty * 8 + r][k];
                unsigned long long a2 = pack2(a, a);
                ffma2(acc[r][0], a2, b0);
                ffma2(acc[r][1], a2, b1v);
            }
        }
        __syncthreads();
    }
    // epilogue: relu + dot(W2) partial per ty group
    float part[4] = {0.f, 0.f, 0.f, 0.f};
#pragma unroll
    for (int r = 0; r < 8; r++) {
        int row = ty * 8 + r;
        float bb = b1[row], w2 = W2[row];
        float2 p0 = unpack2(acc[r][0]);
        float2 p1 = unpack2(acc[r][1]);
        part[0] += fmaxf(p0.x + bb, 0.f) * w2;
        part[1] += fmaxf(p0.y + bb, 0.f) * w2;
        part[2] += fmaxf(p1.x + bb, 0.f) * w2;
        part[3] += fmaxf(p1.y + bb, 0.f) * w2;
    }
#pragma unroll
    for (int c = 0; c < 4; c++) sRed[ty][(tx << 2) + c] = part[c];
    __syncthreads();
    if (tid < 64) {
        float s = 0.f;
#pragma unroll
        for (int y = 0; y < 16; y++) s += sRed[y][tid];
        int col = c0 + tid;
        int f = col / 576; int rem = col - f * 576;
        int v = rem / 24;  int w = rem - v * 24;
        int cnt = nnum[f];
        g_gate[col] = (v < cnt && w < cnt) ? sigm(s + b2p[0]) : 0.f;
    }
}

// ------------ fused message / gate / h_edge / m_v ------------
// grid NFRM*24 (one block per (frame f, receiver v)); 8 warps, lane = sender w.
__global__ void __launch_bounds__(256) msg_k()
{
    int blk = blockIdx.x; int f = blk / 24; int v = blk - f * 24;
    __shared__ float snh[128 * 24];
    __shared__ float sg[24];
    int tid = threadIdx.x;
    for (int i = tid; i < 3072; i += 256) {
        int d = i / 24, w = i - d * 24;
        snh[i] = g_nh[d * NCOLS + f * 24 + w];
    }
    if (tid < 24) sg[tid] = g_gate[f * 576 + v * 24 + tid];
    __syncthreads();

    int wl = tid & 31, dg = tid >> 5;
    bool wok = wl < 24;
    int colbase = f * 576 + v * 24;
#pragma unroll 4
    for (int i = 0; i < 16; i++) {
        int d = dg * 16 + i;
        float gv = 0.f;
        if (wok) {
            int addr = d * ECOLS + colbase + wl;
            float val = fmaxf(snh[d * 24 + wl] + g_epre[addr], 0.f);
            gv = sg[wl] * val;
            g_hedge[addr] = gv;     // h_edge == gated everywhere (masked regions are 0 both ways)
        }
#pragma unroll
        for (int o = 16; o; o >>= 1) gv += __shfl_xor_sync(0xffffffffu, gv, o);
        if (wl == 0) g_mv[d * NCOLS + f * 24 + v] = gv;
    }
}

// ------------ GRU elementwise ------------
__global__ void __launch_bounds__(256) gru_k(const int* __restrict__ nnum)
{
    int idx = blockIdx.x * 256 + threadIdx.x;        // < 128*NCOLS
    int j = idx / NCOLS; int col = idx - j * NCOLS;
    float gir = g_gi[j * NCOLS + col];
    float giz = g_gi[(128 + j) * NCOLS + col];
    float gin = g_gi[(256 + j) * NCOLS + col];
    float ghr = g_gh[j * NCOLS + col];
    float ghz = g_gh[(128 + j) * NCOLS + col];
    float ghn = g_gh[(256 + j) * NCOLS + col];
    float r = sigm(gir + ghr);
    float z = sigm(giz + ghz);
    float n2 = tanhf(gin + r * ghn);
    float h = g_hnode[idx];
    float hn = (1.f - z) * n2 + z * h;
    int f = col / 24; int n = col - f * 24;
    g_hnode[idx] = (n < nnum[f]) ? hn : g_node0[idx];
}

// ------------ LSTM single timestep ------------
// grid 128: rg = blockIdx&15 (8 hidden rows), b = blockIdx>>4. 64 threads.
__global__ void __launch_bounds__(64) lstm_step_k(const float* __restrict__ Whh, int t)
{
    __shared__ float sW[32][129];
    __shared__ float sH[128][25];
    __shared__ float sG[32][25];
    int tid = threadIdx.x;
    int rg = blockIdx.x & 15, b = blockIdx.x >> 4;
    int tr = tid & 7, tc = tid >> 3;
    float acc[4][3];
#pragma unroll
    for (int r = 0; r < 4; r++)
#pragma unroll
        for (int c = 0; c < 3; c++) acc[r][c] = 0.f;

    if (t > 0) {
        for (int i = tid; i < 4096; i += 64) {
            int r = i >> 7, k = i & 127;
            int jg = (r >> 3) * 128 + rg * 8 + (r & 7);
            sW[r][k] = Whh[jg * 128 + k];
        }
        for (int i = tid; i < 3072; i += 64) {
            int j = i / 24, n = i - j * 24;
            sH[j][n] = g_h[j * 192 + b * 24 + n];
        }
        __syncthreads();
#pragma unroll 8
        for (int k = 0; k < 128; k++) {
            float bv[3];
#pragma unroll
            for (int c = 0; c < 3; c++) bv[c] = sH[k][tc * 3 + c];
#pragma unroll
            for (int r = 0; r < 4; r++) {
                float a = sW[tr * 4 + r][k];
#pragma unroll
                for (int c = 0; c < 3; c++) acc[r][c] += a * bv[c];
            }
        }
        __syncthreads();
    }
#pragma unroll
    for (int r = 0; r < 4; r++)
#pragma unroll
        for (int c = 0; c < 3; c++) sG[tr * 4 + r][tc * 3 + c] = acc[r][c];
    __syncthreads();

    for (int e = tid; e < 192; e += 64) {
        int hh = e / 24, n = e - hh * 24;
        int j = rg * 8 + hh;
        int colx = (b * 32 + t) * 24 + n;
        int s = b * 24 + n;
        float ig = sG[hh][n]      + g_xg[(      j) * NCOLS + colx];
        float fg = sG[8 + hh][n]  + g_xg[(128 + j) * NCOLS + colx];
        float gg = sG[16 + hh][n] + g_xg[(256 + j) * NCOLS + colx];
        float og = sG[24 + hh][n] + g_xg[(384 + j) * NCOLS + colx];
        float cold = (t == 0) ? 0.f : g_c[j * 192 + s];
        float cnew = sigm(fg) * cold + sigm(ig) * tanhf(gg);
        float hnew = sigm(og) * tanhf(cnew);
        g_c[j * 192 + s] = cnew;
        g_h[j * 192 + s] = hnew;
        g_hist[j * 6144 + t * 192 + s] = hnew;
    }
}

// ------------ readout: out = (hist^T @ roW^T + rob) * mask ------------
// grid 96, block 256: 64 hist columns per block.
__global__ void __launch_bounds__(256) readout_k(const float* __restrict__ roW,
                                                 const float* __restrict__ rob,
                                                 const int* __restrict__ nnum,
                                                 float* __restrict__ out)
{
    __shared__ float sH[128][65];
    __shared__ float sRo[6][128];
    __shared__ float sRob[6];
    int tid = threadIdx.x;
    int c0 = blockIdx.x * 64;
    for (int i = tid; i < 8192; i += 256) {
        int j = i >> 6, cc = i & 63;
        sH[j][cc] = g_hist[j * 6144 + c0 + cc];
    }
    for (int i = tid; i < 768; i += 256) sRo[i >> 7][i & 127] = roW[i];
    if (tid < 6) sRob[tid] = rob[tid];
    __syncthreads();
    for (int e = tid; e < 384; e += 256) {
        int cc = e / 6, c = e - cc * 6;
        float s = 0.f;
#pragma unroll 8
        for (int j = 0; j < 128; j++) s += sRo[c][j] * sH[j][cc];
        int ct = c0 + cc;
        int t = ct / 192; int srem = ct - t * 192;
        int b = srem / 24; int n = srem - b * 24;
        int f = b * 32 + t;
        out[(f * 24 + n) * 6 + c] = (n < nnum[f]) ? (s + sRob[c]) : 0.f;
    }
}

// ------------ host launcher ------------
extern "C" void kernel_launch(void* const* d_in, const int* in_sizes, int n_in,
                              void* d_out, int out_size)
{
    const float* node     = (const float*)d_in[0];
    const float* edge     = (const float*)d_in[1];
    const float* link_W1  = (const float*)d_in[2];
    const float* link_b1  = (const float*)d_in[3];
    const float* link_W2  = (const float*)d_in[4];
    const float* link_b2  = (const float*)d_in[5];
    const float* msg_Wh   = (const float*)d_in[6];
    const float* msg_We   = (const float*)d_in[7];
    const float* msg_b    = (const float*)d_in[8];
    const float* gru_Wih  = (const float*)d_in[9];
    const float* gru_Whh  = (const float*)d_in[10];
    const float* gru_bih  = (const float*)d_in[11];
    const float* gru_bhh  = (const float*)d_in[12];
    const float* lstm_Wih = (const float*)d_in[13];
    const float* lstm_Whh = (const float*)d_in[14];
    const float* lstm_bih = (const float*)d_in[15];
    const float* lstm_bhh = (const float*)d_in[16];
    const float* ro_W     = (const float*)d_in[17];
    const float* ro_b     = (const float*)d_in[18];
    const int*   nnum     = (const int*)d_in[19];
    float* out = (float*)d_out;

    float* edge_t; cudaGetSymbolAddress((void**)&edge_t, g_edge_t);
    float* epre;   cudaGetSymbolAddress((void**)&epre,   g_epre);
    float* hedge;  cudaGetSymbolAddress((void**)&hedge,  g_hedge);
    float* hnode;  cudaGetSymbolAddress((void**)&hnode,  g_hnode);
    float* nh;     cudaGetSymbolAddress((void**)&nh,     g_nh);
    float* mv;     cudaGetSymbolAddress((void**)&mv,     g_mv);
    float* gi;     cudaGetSymbolAddress((void**)&gi,     g_gi);
    float* gh;     cudaGetSymbolAddress((void**)&gh,     g_gh);
    float* xg;     cudaGetSymbolAddress((void**)&xg,     g_xg);

    tr_edge_k<<<(128 * ECOLS) / 256, 256>>>(edge);
    tr_node_k<<<(128 * NCOLS) / 256, 256>>>(node);

    // loop-invariant: epre = msg_We @ edge_t + msg_b
    sgemm_k<<<dim3(ECOLS / 64, 2), 256>>>(msg_We, edge_t, msg_b, nullptr, epre, ECOLS);

    for (int p = 0; p < 3; p++) {
        link_k<<<ECOLS / 64, 256>>>(p == 0 ? edge_t : hedge,
                                    link_W1, link_b1, link_W2, link_b2, nnum);
        sgemm_k<<<dim3(NCOLS / 64, 2), 256>>>(msg_Wh, hnode, nullptr, nullptr, nh, NCOLS);
        msg_k<<<NFRM * 24, 256>>>();
        sgemm_k<<<dim3(NCOLS / 64, 6), 256>>>(gru_Wih, mv,    gru_bih, nullptr, gi, NCOLS);
        sgemm_k<<<dim3(NCOLS / 64, 6), 256>>>(gru_Whh, hnode, gru_bhh, nullptr, gh, NCOLS);
        gru_k<<<(128 * NCOLS) / 256, 256>>>(nnum);
    }

    // LSTM input projection for all timesteps, biases folded
    sgemm_k<<<dim3(NCOLS / 64, 8), 256>>>(lstm_Wih, hnode, lstm_bih, lstm_bhh, xg, NCOLS);

    for (int t = 0; t < 32; t++)
        lstm_step_k<<<128, 64>>>(lstm_Whh, t);

    readout_k<<<96, 256>>>(ro_W, ro_b, nnum, out);
    (void)in_sizes; (void)n_in; (void)out_size;
}